// round 1
// baseline (speedup 1.0000x reference)
#include <cuda_runtime.h>
#include <math.h>

// DegreeSortedMambaLayer — full fp32 pipeline
// G=64 graphs x N=256 nodes, DM=256, DI=512, DS=16, DTR=16, DC=4

#define NTOT 16384
#define NGRAPH 64
#define NNODE 256
#define DMODEL 256
#define DINNER 512
#define DSTATE 16

// ------------------------- scratch (device globals; no allocs) -------------
__device__ float g_XZ[(size_t)NTOT * 1024];   // in_proj output [xc | z]
__device__ float g_U [(size_t)NTOT * 512];    // conv+silu output
__device__ float g_P [(size_t)NTOT * 64];     // xproj output (48 used, padded to 64)
__device__ float g_Y [(size_t)NTOT * 512];    // scan output (pre out_proj)
__device__ float g_F [(size_t)NTOT * 256];    // forward mamba output
__device__ float g_B [(size_t)NTOT * 256];    // backward mamba output (flipped order)
__device__ int   g_deg[NTOT];
__device__ int   g_permF[NTOT];
__device__ int   g_permB[NTOT];
__device__ float g_xpad[64 * 512];            // padded xproj weights

// ------------------------- fast math (FMA-only, no MUFU) -------------------
__device__ __forceinline__ float fexp(float x) {
    // exp(x) = 2^(x*log2e); 2^f via degree-6 poly + exponent bit insert
    x = fminf(fmaxf(x, -87.0f), 88.0f);
    float t = x * 1.4426950408889634f;
    float fl = floorf(t);
    float f = t - fl;
    float p = fmaf(f, 1.5403530e-4f, 1.3333558e-3f);
    p = fmaf(f, p, 9.6181291e-3f);
    p = fmaf(f, p, 5.5504109e-2f);
    p = fmaf(f, p, 2.4022651e-1f);
    p = fmaf(f, p, 6.9314718e-1f);
    p = fmaf(f, p, 1.0f);
    return __int_as_float(__float_as_int(p) + (((int)fl) << 23));
}

__device__ __forceinline__ float frcp(float a) {
    float r = __int_as_float(0x7EF311C3 - __float_as_int(a));
    r = r * (2.0f - a * r);
    r = r * (2.0f - a * r);
    r = r * (2.0f - a * r);
    return r;
}

__device__ __forceinline__ float fsig(float v) {
    return frcp(1.0f + fexp(-v));
}

__device__ __forceinline__ float fsoftplus(float x) {
    float e = fexp(x);
    if (e < 0.25f) {
        // log1p(e), alternating series to degree 7
        float p = fmaf(e, 0.142857143f, -0.166666667f);
        p = fmaf(e, p, 0.2f);
        p = fmaf(e, p, -0.25f);
        p = fmaf(e, p, 0.333333333f);
        p = fmaf(e, p, -0.5f);
        p = fmaf(e, p, 1.0f);
        return e * p;
    }
    return __logf(1.0f + e);
}

// ------------------------- degree + sort -----------------------------------
__global__ void deg_zero(int* deg) {
    deg[blockIdx.x * 256 + threadIdx.x] = 0;
}

__global__ void deg_count(const int* __restrict__ ei, int* __restrict__ deg, int ne) {
    int i = blockIdx.x * 256 + threadIdx.x;
    if (i < ne) atomicAdd(&deg[ei[i]], 1);
}

// stable sort by degree within each graph: unique key = (deg<<8)|local_idx
__global__ void sort_graphs(const int* __restrict__ deg,
                            int* __restrict__ permF, int* __restrict__ permB) {
    __shared__ unsigned key[256];
    int g = blockIdx.x, tid = threadIdx.x;
    key[tid] = (((unsigned)deg[g * 256 + tid]) << 8) | (unsigned)tid;
    __syncthreads();
    for (int k = 2; k <= 256; k <<= 1) {
        for (int j = k >> 1; j > 0; j >>= 1) {
            int ixj = tid ^ j;
            if (ixj > tid) {
                unsigned a = key[tid], b = key[ixj];
                bool asc = ((tid & k) == 0);
                if ((a > b) == asc) { key[tid] = b; key[ixj] = a; }
            }
            __syncthreads();
        }
    }
    permF[g * 256 + tid] = g * 256 + (int)(key[tid] & 255u);
    permB[g * 256 + tid] = g * 256 + (int)(key[255 - tid] & 255u);
}

// ------------------------- SGEMM: C[M,N] = A[M,K] (gathered) @ W[N,K]^T ----
template <int BN, int TN>
__global__ void __launch_bounds__(256) sgemm_nt(
    const float* __restrict__ A, const float* __restrict__ W,
    float* __restrict__ C, int K, int N, const int* __restrict__ rowmap)
{
    constexpr int BM = 128, BK = 16, TM = 8;
    __shared__ float As[BK][BM];
    __shared__ float Ws[BK][BN];
    int tid = threadIdx.x;
    int tx = tid & 15, ty = tid >> 4;
    int m0 = blockIdx.y * BM, n0 = blockIdx.x * BN;

    float acc[TM][TN];
#pragma unroll
    for (int i = 0; i < TM; i++)
#pragma unroll
        for (int j = 0; j < TN; j++) acc[i][j] = 0.0f;

    for (int k0 = 0; k0 < K; k0 += BK) {
        __syncthreads();
#pragma unroll
        for (int l = 0; l < 2; l++) {           // A tile: 128x16 = 512 float4
            int i = tid + 256 * l;
            int row = i >> 2, kq = i & 3;
            int m = m0 + row;
            int gr = rowmap ? rowmap[m] : m;
            float4 v = *reinterpret_cast<const float4*>(A + (size_t)gr * K + k0 + kq * 4);
            As[kq * 4 + 0][row] = v.x; As[kq * 4 + 1][row] = v.y;
            As[kq * 4 + 2][row] = v.z; As[kq * 4 + 3][row] = v.w;
        }
#pragma unroll
        for (int l = 0; l < BN / 64; l++) {     // W tile: BNx16 = BN*4 float4
            int i = tid + 256 * l;
            int row = i >> 2, kq = i & 3;
            float4 v = *reinterpret_cast<const float4*>(W + (size_t)(n0 + row) * K + k0 + kq * 4);
            Ws[kq * 4 + 0][row] = v.x; Ws[kq * 4 + 1][row] = v.y;
            Ws[kq * 4 + 2][row] = v.z; Ws[kq * 4 + 3][row] = v.w;
        }
        __syncthreads();
#pragma unroll
        for (int k = 0; k < BK; k++) {
            float a[TM], b[TN];
#pragma unroll
            for (int i = 0; i < TM; i++) a[i] = As[k][ty * TM + i];
#pragma unroll
            for (int j = 0; j < TN; j++) b[j] = Ws[k][tx * TN + j];
#pragma unroll
            for (int i = 0; i < TM; i++)
#pragma unroll
                for (int j = 0; j < TN; j++) acc[i][j] = fmaf(a[i], b[j], acc[i][j]);
        }
    }
#pragma unroll
    for (int i = 0; i < TM; i++) {
        int m = m0 + ty * TM + i;
#pragma unroll
        for (int j = 0; j < TN; j += 4) {
            float4 v = make_float4(acc[i][j], acc[i][j + 1], acc[i][j + 2], acc[i][j + 3]);
            *reinterpret_cast<float4*>(C + (size_t)m * N + n0 + tx * TN + j) = v;
        }
    }
}

// ------------------------- pad xproj weights to N=64 ----------------------
__global__ void xpad_build(const float* __restrict__ xw, float* __restrict__ xpad) {
    int i = blockIdx.x * 256 + threadIdx.x;   // 32768 total
    xpad[i] = (i < 48 * 512) ? xw[i] : 0.0f;
}

// ------------------------- causal depthwise conv + silu -------------------
__global__ void conv_silu(const float* __restrict__ XZ, const float* __restrict__ cw,
                          const float* __restrict__ cb, float* __restrict__ U) {
    int idx = blockIdx.x * 256 + threadIdx.x;    // NTOT*512 threads
    int d = idx & 511, r = idx >> 9, t = r & 255;
    const float* base = XZ + (size_t)r * 1024 + d;
    float4 w = *reinterpret_cast<const float4*>(cw + d * 4);
    float s = cb[d];
    if (t >= 3) s = fmaf(base[-3 * 1024], w.x, s);
    if (t >= 2) s = fmaf(base[-2 * 1024], w.y, s);
    if (t >= 1) s = fmaf(base[-1 * 1024], w.z, s);
    s = fmaf(base[0], w.w, s);
    U[(size_t)r * 512 + d] = s * fsig(s);
}

// ------------------------- selective scan (delta folded in) ---------------
// grid: (8 d-chunks, 64 graphs), 64 threads/block, one d per thread
__global__ void __launch_bounds__(64) scan_kernel(
    const float* __restrict__ P, const float* __restrict__ U,
    const float* __restrict__ XZ,
    const float* __restrict__ dtw_g, const float* __restrict__ dtb_g,
    const float* __restrict__ Alog, const float* __restrict__ Dp,
    float* __restrict__ Y)
{
    int b = blockIdx.y;
    int tid = threadIdx.x;
    int d = blockIdx.x * 64 + tid;

    float dtw[16], a[16], h[16];
#pragma unroll
    for (int j = 0; j < 16; j++) {
        dtw[j] = dtw_g[d * 16 + j];
        a[j] = -expf(Alog[d * 16 + j]);
        h[j] = 0.0f;
    }
    float dtb = dtb_g[d], dp = Dp[d];

    __shared__ float sp[2][48];
    int r0 = b * 256;
    if (tid < 48) sp[0][tid] = P[(size_t)r0 * 64 + tid];
    __syncthreads();

    for (int t = 0; t < 256; t++) {
        int cur = t & 1;
        if (t < 255 && tid < 48) sp[cur ^ 1][tid] = P[(size_t)(r0 + t + 1) * 64 + tid];
        int r = r0 + t;
        float acc = dtb;
#pragma unroll
        for (int j = 0; j < 16; j++) acc = fmaf(sp[cur][j], dtw[j], acc);
        float delta = fsoftplus(acc);
        float u = U[(size_t)r * 512 + d];
        float z = XZ[(size_t)r * 1024 + 512 + d];
        float du = delta * u;
        float y = 0.0f;
#pragma unroll
        for (int s = 0; s < 16; s++) {
            float dA = fexp(delta * a[s]);
            h[s] = fmaf(dA, h[s], du * sp[cur][16 + s]);
            y = fmaf(h[s], sp[cur][32 + s], y);
        }
        float sz = z * fsig(z);
        Y[(size_t)r * 512 + d] = (y + u * dp) * sz;
        __syncthreads();
    }
}

// ------------------------- gate GEMM + fuse + scatter ---------------------
// A[m,k] = concat(F[m], B[m^255]); C = sigmoid(A @ gate_w^T + b); out scatter
__global__ void __launch_bounds__(256) gate_gemm(
    const float* __restrict__ F, const float* __restrict__ Bo,
    const float* __restrict__ Wg, const float* __restrict__ bg,
    const int* __restrict__ perm, float* __restrict__ out)
{
    constexpr int BM = 128, BN = 128, BK = 16, K = 512;
    __shared__ float As[BK][BM];
    __shared__ float Ws[BK][BN];
    int tid = threadIdx.x;
    int tx = tid & 15, ty = tid >> 4;
    int m0 = blockIdx.y * BM, n0 = blockIdx.x * BN;

    float acc[8][8];
#pragma unroll
    for (int i = 0; i < 8; i++)
#pragma unroll
        for (int j = 0; j < 8; j++) acc[i][j] = 0.0f;

    for (int k0 = 0; k0 < K; k0 += BK) {
        __syncthreads();
#pragma unroll
        for (int l = 0; l < 2; l++) {
            int i = tid + 256 * l;
            int row = i >> 2, kq = i & 3;
            int k = k0 + kq * 4;
            int m = m0 + row;
            const float* src = (k < 256) ? (F + (size_t)m * 256 + k)
                                         : (Bo + (size_t)(m ^ 255) * 256 + (k - 256));
            float4 v = *reinterpret_cast<const float4*>(src);
            As[kq * 4 + 0][row] = v.x; As[kq * 4 + 1][row] = v.y;
            As[kq * 4 + 2][row] = v.z; As[kq * 4 + 3][row] = v.w;
        }
#pragma unroll
        for (int l = 0; l < 2; l++) {
            int i = tid + 256 * l;
            int row = i >> 2, kq = i & 3;
            float4 v = *reinterpret_cast<const float4*>(Wg + (size_t)(n0 + row) * K + k0 + kq * 4);
            Ws[kq * 4 + 0][row] = v.x; Ws[kq * 4 + 1][row] = v.y;
            Ws[kq * 4 + 2][row] = v.z; Ws[kq * 4 + 3][row] = v.w;
        }
        __syncthreads();
#pragma unroll
        for (int k = 0; k < BK; k++) {
            float a[8], b[8];
#pragma unroll
            for (int i = 0; i < 8; i++) a[i] = As[k][ty * 8 + i];
#pragma unroll
            for (int j = 0; j < 8; j++) b[j] = Ws[k][tx * 8 + j];
#pragma unroll
            for (int i = 0; i < 8; i++)
#pragma unroll
                for (int j = 0; j < 8; j++) acc[i][j] = fmaf(a[i], b[j], acc[i][j]);
        }
    }
    // epilogue: g = sigmoid(acc + bias); y = b + g*(f-b); scatter by perm
#pragma unroll
    for (int i = 0; i < 8; i++) {
        int m = m0 + ty * 8 + i;
        const float* fr = F + (size_t)m * 256;
        const float* br = Bo + (size_t)(m ^ 255) * 256;
        float* orow = out + (size_t)perm[m] * 256;
#pragma unroll
        for (int jj = 0; jj < 8; jj += 4) {
            int n = n0 + tx * 8 + jj;
            float4 res;
            {
                float g0 = fsig(acc[i][jj + 0] + bg[n + 0]);
                float g1 = fsig(acc[i][jj + 1] + bg[n + 1]);
                float g2 = fsig(acc[i][jj + 2] + bg[n + 2]);
                float g3 = fsig(acc[i][jj + 3] + bg[n + 3]);
                float4 fv = *reinterpret_cast<const float4*>(fr + n);
                float4 bv = *reinterpret_cast<const float4*>(br + n);
                res.x = fmaf(g0, fv.x - bv.x, bv.x);
                res.y = fmaf(g1, fv.y - bv.y, bv.y);
                res.z = fmaf(g2, fv.z - bv.z, bv.z);
                res.w = fmaf(g3, fv.w - bv.w, bv.w);
            }
            *reinterpret_cast<float4*>(orow + n) = res;
        }
    }
}

// ------------------------- host ------------------------------------------
extern "C" void kernel_launch(void* const* d_in, const int* in_sizes, int n_in,
                              void* d_out, int out_size) {
    const float* x      = (const float*)d_in[0];
    const int*   ei     = (const int*)d_in[1];
    const float* gate_w = (const float*)d_in[3];
    const float* gate_b = (const float*)d_in[4];

    struct MW { const float *in_w, *conv_w, *conv_b, *xproj_w, *dt_w, *dt_b, *A_log, *Dp, *out_w; };
    MW fw = { (const float*)d_in[5],  (const float*)d_in[6],  (const float*)d_in[7],
              (const float*)d_in[8],  (const float*)d_in[9],  (const float*)d_in[10],
              (const float*)d_in[11], (const float*)d_in[12], (const float*)d_in[13] };
    MW bw = { (const float*)d_in[14], (const float*)d_in[15], (const float*)d_in[16],
              (const float*)d_in[17], (const float*)d_in[18], (const float*)d_in[19],
              (const float*)d_in[20], (const float*)d_in[21], (const float*)d_in[22] };

    int ne = in_sizes[1] / 2;

    float *XZ, *U, *P, *Y, *F, *B, *xpad;
    int *deg, *permF, *permB;
    cudaGetSymbolAddress((void**)&XZ, g_XZ);
    cudaGetSymbolAddress((void**)&U,  g_U);
    cudaGetSymbolAddress((void**)&P,  g_P);
    cudaGetSymbolAddress((void**)&Y,  g_Y);
    cudaGetSymbolAddress((void**)&F,  g_F);
    cudaGetSymbolAddress((void**)&B,  g_B);
    cudaGetSymbolAddress((void**)&xpad, g_xpad);
    cudaGetSymbolAddress((void**)&deg,   g_deg);
    cudaGetSymbolAddress((void**)&permF, g_permF);
    cudaGetSymbolAddress((void**)&permB, g_permB);

    deg_zero<<<NTOT / 256, 256>>>(deg);
    deg_count<<<(ne + 255) / 256, 256>>>(ei, deg, ne);
    sort_graphs<<<NGRAPH, 256>>>(deg, permF, permB);

    const MW* dirs[2] = { &fw, &bw };
    const int* rms[2] = { permF, permB };
    float* douts[2]   = { F, B };

    for (int dir = 0; dir < 2; dir++) {
        const MW& w = *dirs[dir];
        xpad_build<<<128, 256>>>(w.xproj_w, xpad);
        // in_proj: XZ = x[perm] @ in_w^T   [16384 x 1024], K=256
        sgemm_nt<128, 8><<<dim3(8, 128), 256>>>(x, w.in_w, XZ, 256, 1024, rms[dir]);
        // causal conv + silu -> U [16384 x 512]
        conv_silu<<<(NTOT * 512) / 256, 256>>>(XZ, w.conv_w, w.conv_b, U);
        // xproj: P = U @ xpad^T  [16384 x 64], K=512
        sgemm_nt<64, 4><<<dim3(1, 128), 256>>>(U, xpad, P, 512, 64, nullptr);
        // selective scan (delta projection folded in) -> Y [16384 x 512]
        scan_kernel<<<dim3(8, NGRAPH), 64>>>(P, U, XZ, w.dt_w, w.dt_b, w.A_log, w.Dp, Y);
        // out_proj: OUT = Y @ out_w^T  [16384 x 256], K=512
        sgemm_nt<128, 8><<<dim3(2, 128), 256>>>(Y, w.out_w, douts[dir], 512, 256, nullptr);
    }

    // gate fusion + scatter to original node order
    gate_gemm<<<dim3(2, 128), 256>>>(F, B, gate_w, gate_b, permF, (float*)d_out);
}